// round 2
// baseline (speedup 1.0000x reference)
#include <cuda_runtime.h>
#include <cstdint>
#include <cstddef>

#define BB 8
#define LL 2048
#define HH 8
#define DD 64
#define EE 33
#define UU 40
#define SK 40
#define BHN (BB*HH)
#define ROWS (BHN*LL)

// ---------------- static scratch ----------------
__device__ float2 g_qf [ROWS*EE];
__device__ float2 g_kf [ROWS*EE];
__device__ float2 g_vf [ROWS*EE];
__device__ float2 g_kfT[ROWS*EE];
__device__ float  g_M  [ROWS];
__device__ int    g_top [BHN*UU];
__device__ int    g_slot[ROWS];
__device__ float2 g_upd [BHN*UU*EE];
__device__ float2 g_vmean[BHN*EE];
__device__ float  g_vmt[BHN*DD];
__device__ float2 g_big [(size_t)BHN*UU*LL];

// ---------------- K1: rfft of q,k,v (warp per row, direct DFT) ----------------
__global__ void k_rfft(const float* __restrict__ q,
                       const float* __restrict__ k,
                       const float* __restrict__ v)
{
    __shared__ float tc[64], ts[64];
    __shared__ float xs[8][64];
    int tid = threadIdx.x;
    if (tid < 64) {
        float s, c;
        sincospif(tid * (1.0f/32.0f), &s, &c);   // 2*pi*tid/64
        tc[tid] = c; ts[tid] = s;
    }
    __syncthreads();
    int warp = tid >> 5, lane = tid & 31;
    int r  = blockIdx.x * 8 + warp;              // r = bh*L + l
    int l  = r & (LL - 1);
    int bh = r >> 11;
    int b = bh >> 3, h = bh & 7;
    const float* src = (blockIdx.y == 0) ? q : (blockIdx.y == 1) ? k : v;
    const float* x = src + (((size_t)b*LL + l)*HH + h) * DD;
    float x0 = x[lane], x1 = x[lane + 32];
    xs[warp][lane] = x0; xs[warp][lane + 32] = x1;
    __syncwarp();
    int e = lane;
    float ar = 0.f, ai = 0.f;
    int j = 0;
    #pragma unroll
    for (int d = 0; d < 64; ++d) {
        float xv = xs[warp][d];
        ar = fmaf(xv, tc[j], ar);
        ai = fmaf(xv, -ts[j], ai);
        j = (j + e) & 63;
    }
    // e=32 bin: sum (-1)^d x_d ; d=lane and d=lane+32 share parity
    float p = x0 + x1;
    float sg = (lane & 1) ? -p : p;
    #pragma unroll
    for (int o = 16; o; o >>= 1) sg += __shfl_xor_sync(0xffffffffu, sg, o);
    float2* out = (blockIdx.y == 0) ? g_qf : (blockIdx.y == 1) ? g_kf : g_vf;
    out[(size_t)r*EE + lane] = make_float2(ar, ai);
    if (lane == 0) out[(size_t)r*EE + 32] = make_float2(sg, 0.f);
}

// ---------------- K2: transpose k_fft -> (bh, e, l) ----------------
__global__ void k_transpose()
{
    __shared__ float2 tile[32][EE];
    int bh = blockIdx.y;
    int l0 = blockIdx.x * 32;
    for (int t = threadIdx.x; t < 32*EE; t += 256) {
        int r = t / EE, e = t - r*EE;
        tile[r][e] = g_kf[((size_t)bh*LL + l0 + r)*EE + e];
    }
    __syncthreads();
    for (int t = threadIdx.x; t < EE*32; t += 256) {
        int e = t >> 5, r = t & 31;
        g_kfT[((size_t)bh*EE + e)*LL + l0 + r] = tile[r][e];
    }
}

// ---------------- K2b: v mean over L ----------------
__global__ void k_vmean()
{
    int bh = blockIdx.x;
    int t = threadIdx.x;
    if (t >= 2*EE) return;
    const float* vb = (const float*)g_vf + (size_t)bh*LL*(2*EE);
    float acc = 0.f;
    #pragma unroll 4
    for (int l = 0; l < LL; ++l) acc += vb[(size_t)l*(2*EE) + t];
    ((float*)g_vmean)[bh*(2*EE) + t] = acc * (1.0f/LL);
}

// ---------------- K3: sampled QK -> M score (warp per (bh,l)) ----------------
__global__ void __launch_bounds__(128) k_msample(const int* __restrict__ isamp)
{
    __shared__ float2 kbuf[4][SK][EE];
    __shared__ float2 qbuf[4][EE];
    int tid = threadIdx.x;
    int warp = tid >> 5, lane = tid & 31;
    int r  = blockIdx.x * 4 + warp;
    int l  = r & (LL - 1);
    int bh = r >> 11;
    const int* iss = isamp + l * SK;
    int idxA = iss[lane];
    int idxB = (lane < 8) ? iss[32 + lane] : 0;
    size_t qb = (size_t)r * EE;
    qbuf[warp][lane] = g_qf[qb + lane];
    if (lane == 0) qbuf[warp][32] = g_qf[qb + 32];
    const float2* kbase = g_kf + (size_t)bh*LL*EE;
    #pragma unroll 4
    for (int s = 0; s < SK; ++s) {
        int id = (s < 32) ? __shfl_sync(0xffffffffu, idxA, s)
                          : __shfl_sync(0xffffffffu, idxB, s - 32);
        const float2* krow = kbase + (size_t)id*EE;
        kbuf[warp][s][lane] = krow[lane];
        if (lane == 0) kbuf[warp][s][32] = krow[32];
    }
    __syncwarp();
    float reA = 0.f, imA = 0.f;
    #pragma unroll
    for (int e = 0; e < EE; ++e) {
        float2 kv = kbuf[warp][lane][e];
        float2 qv = qbuf[warp][e];
        reA = fmaf(qv.x, kv.x, reA); reA = fmaf(-qv.y, kv.y, reA);
        imA = fmaf(qv.x, kv.y, imA); imA = fmaf( qv.y, kv.x, imA);
    }
    float mre = reA, mim = imA, sre = reA, sim = imA;
    if (lane < 8) {
        float reB = 0.f, imB = 0.f;
        #pragma unroll
        for (int e = 0; e < EE; ++e) {
            float2 kv = kbuf[warp][32 + lane][e];
            float2 qv = qbuf[warp][e];
            reB = fmaf(qv.x, kv.x, reB); reB = fmaf(-qv.y, kv.y, reB);
            imB = fmaf(qv.x, kv.y, imB); imB = fmaf( qv.y, kv.x, imB);
        }
        mre = fmaxf(mre, reB); mim = fmaxf(mim, imB);
        sre += reB; sim += imB;
    }
    #pragma unroll
    for (int o = 16; o; o >>= 1) {
        mre = fmaxf(mre, __shfl_xor_sync(0xffffffffu, mre, o));
        mim = fmaxf(mim, __shfl_xor_sync(0xffffffffu, mim, o));
        sre += __shfl_xor_sync(0xffffffffu, sre, o);
        sim += __shfl_xor_sync(0xffffffffu, sim, o);
    }
    if (lane == 0) g_M[r] = mre + mim - (sre + sim) * (1.0f/LL);
}

// ---------------- K4: top-40 per bh + slot map ----------------
__global__ void k_topk()
{
    __shared__ float mv[LL];
    __shared__ float rv[256];
    __shared__ int   ri[256];
    int bh = blockIdx.x, tid = threadIdx.x;
    for (int i = tid; i < LL; i += 256) {
        mv[i] = g_M[bh*LL + i];
        g_slot[bh*LL + i] = -1;
    }
    __syncthreads();
    for (int u = 0; u < UU; ++u) {
        float best = -3.4e38f; int bi = LL;
        for (int i = tid; i < LL; i += 256) {
            float v = mv[i];
            if (v > best) { best = v; bi = i; }     // keep earliest in-stride
        }
        rv[tid] = best; ri[tid] = bi;
        __syncthreads();
        for (int s = 128; s; s >>= 1) {
            if (tid < s) {
                float ov = rv[tid+s]; int oi = ri[tid+s];
                if (ov > rv[tid] || (ov == rv[tid] && oi < ri[tid])) { rv[tid] = ov; ri[tid] = oi; }
            }
            __syncthreads();
        }
        if (tid == 0) {
            int w = ri[0];
            g_top[bh*UU + u] = w;
            g_slot[bh*LL + w] = u;
            mv[w] = -3.4e38f;
        }
        __syncthreads();
    }
}

// ---------------- K5: full scores, 20-u register blocked ----------------
__global__ void __launch_bounds__(512) k_scores()
{
    __shared__ float2 shq[20][EE];
    int bh = blockIdx.z;
    int ug = blockIdx.y;     // 0..1
    int jt = blockIdx.x;     // 0..3
    int tid = threadIdx.x;
    for (int t = tid; t < 20*EE; t += 512) {
        int ul = t / EE, e = t - ul*EE;
        int qi = g_top[bh*UU + ug*20 + ul];
        shq[ul][e] = g_qf[((size_t)bh*LL + qi)*EE + e];
    }
    __syncthreads();
    int j = jt*512 + tid;
    float accR[20], accI[20];
    #pragma unroll
    for (int u = 0; u < 20; ++u) { accR[u] = 0.f; accI[u] = 0.f; }
    const float2* kT = g_kfT + (size_t)bh*EE*LL + j;
    for (int e = 0; e < EE; ++e) {
        float2 kv = kT[(size_t)e*LL];
        #pragma unroll
        for (int u = 0; u < 20; ++u) {
            float2 qv = shq[u][e];
            accR[u] = fmaf(qv.x, kv.x, accR[u]); accR[u] = fmaf(-qv.y, kv.y, accR[u]);
            accI[u] = fmaf(qv.x, kv.y, accI[u]); accI[u] = fmaf( qv.y, kv.x, accI[u]);
        }
    }
    const float sc = 0.125f;   // 1/sqrt(64)
    #pragma unroll
    for (int u = 0; u < 20; ++u)
        g_big[((size_t)bh*UU + ug*20 + u)*LL + j] = make_float2(accR[u]*sc, accI[u]*sc);
}

// ---------------- K5b: softmax over real & imag channels ----------------
__global__ void k_softmax()
{
    __shared__ float2 sb[LL];
    __shared__ float2 red[256];
    int row = blockIdx.x, tid = threadIdx.x;
    float2* rp = g_big + (size_t)row*LL;
    float mr = -3.4e38f, mi = -3.4e38f;
    for (int i = tid; i < LL; i += 256) {
        float2 v = rp[i]; sb[i] = v;
        mr = fmaxf(mr, v.x); mi = fmaxf(mi, v.y);
    }
    red[tid] = make_float2(mr, mi);
    __syncthreads();
    for (int s = 128; s; s >>= 1) {
        if (tid < s) {
            red[tid].x = fmaxf(red[tid].x, red[tid+s].x);
            red[tid].y = fmaxf(red[tid].y, red[tid+s].y);
        }
        __syncthreads();
    }
    mr = red[0].x; mi = red[0].y;
    __syncthreads();
    float sr = 0.f, si = 0.f;
    for (int i = tid; i < LL; i += 256) {
        float er = expf(sb[i].x - mr);
        float ei = expf(sb[i].y - mi);
        sb[i] = make_float2(er, ei);
        sr += er; si += ei;
    }
    red[tid] = make_float2(sr, si);
    __syncthreads();
    for (int s = 128; s; s >>= 1) {
        if (tid < s) { red[tid].x += red[tid+s].x; red[tid].y += red[tid+s].y; }
        __syncthreads();
    }
    float inr = 1.0f / red[0].x, ini = 1.0f / red[0].y;
    for (int i = tid; i < LL; i += 256)
        rp[i] = make_float2(sb[i].x * inr, sb[i].y * ini);
}

// ---------------- K6: upd = attn_r @ v.re  +  i * attn_i @ v.im ----------------
__global__ void __launch_bounds__(256) k_upd()
{
    __shared__ float2 sp[8][256];
    __shared__ float2 accs[8][8][EE];
    int bh = blockIdx.y, ug = blockIdx.x;
    int tid = threadIdx.x, warp = tid >> 5, lane = tid & 31;
    float aR[8], aI[8], aR2[8], aI2[8];
    #pragma unroll
    for (int u = 0; u < 8; ++u) { aR[u]=aI[u]=aR2[u]=aI2[u]=0.f; }
    const float2* vb = g_vf + (size_t)bh*LL*EE;
    for (int c = 0; c < 8; ++c) {
        #pragma unroll
        for (int u = 0; u < 8; ++u)
            sp[u][tid] = g_big[((size_t)bh*UU + ug*8 + u)*LL + c*256 + tid];
        __syncthreads();
        for (int li = warp; li < 256; li += 8) {
            int l = c*256 + li;
            float2 v2 = vb[(size_t)l*EE + lane];
            float2 v32 = make_float2(0.f, 0.f);
            if (lane == 0) v32 = vb[(size_t)l*EE + 32];
            #pragma unroll
            for (int u = 0; u < 8; ++u) {
                float2 p = sp[u][li];
                aR[u] = fmaf(p.x, v2.x, aR[u]);
                aI[u] = fmaf(p.y, v2.y, aI[u]);
                aR2[u] = fmaf(p.x, v32.x, aR2[u]);
                aI2[u] = fmaf(p.y, v32.y, aI2[u]);
            }
        }
        __syncthreads();
    }
    #pragma unroll
    for (int u = 0; u < 8; ++u) {
        accs[warp][u][lane] = make_float2(aR[u], aI[u]);
        if (lane == 0) accs[warp][u][32] = make_float2(aR2[u], aI2[u]);
    }
    __syncthreads();
    for (int t = tid; t < 8*EE; t += 256) {
        int u = t / EE, e = t - u*EE;
        float sr = 0.f, si = 0.f;
        #pragma unroll
        for (int w = 0; w < 8; ++w) { sr += accs[w][u][e].x; si += accs[w][u][e].y; }
        g_upd[((size_t)bh*UU + ug*8 + u)*EE + e] = make_float2(sr, si);
    }
}

// ---------------- K7a: irfft of v-mean (once per bh) ----------------
__global__ void k_vmt()
{
    __shared__ float tc[64], ts[64];
    int d = threadIdx.x;
    {
        float s, c;
        sincospif(d * (1.0f/32.0f), &s, &c);
        tc[d] = c; ts[d] = s;
    }
    __syncthreads();
    int bh = blockIdx.x;
    const float2* X = g_vmean + bh*EE;
    float acc = X[0].x + ((d & 1) ? -X[32].x : X[32].x);
    #pragma unroll
    for (int e = 1; e < 32; ++e) {
        float2 Xe = X[e];
        int j = (e*d) & 63;
        acc += 2.f * (Xe.x*tc[j] - Xe.y*ts[j]);
    }
    g_vmt[bh*DD + d] = acc * (1.0f/64.0f);
}

// ---------------- K7b: scatter + irfft of selected rows ----------------
__global__ void k_out(float* __restrict__ out)
{
    __shared__ float tc[64], ts[64];
    __shared__ float2 ub[8][EE];
    int tid = threadIdx.x;
    if (tid < 64) {
        float s, c;
        sincospif(tid * (1.0f/32.0f), &s, &c);
        tc[tid] = c; ts[tid] = s;
    }
    __syncthreads();
    int warp = tid >> 5, lane = tid & 31;
    int r = blockIdx.x * 8 + warp;
    int bh = r >> 11;
    int slot = g_slot[r];
    float* op = out + (size_t)r * DD;
    if (slot < 0) {
        op[lane]      = g_vmt[bh*DD + lane];
        op[lane + 32] = g_vmt[bh*DD + lane + 32];
    } else {
        const float2* X = g_upd + ((size_t)bh*UU + slot)*EE;
        ub[warp][lane] = X[lane];
        if (lane == 0) ub[warp][32] = X[32];
        __syncwarp();
        float a0 = ub[warp][0].x;
        float a32 = ub[warp][32].x;
        float sgn = (lane & 1) ? -a32 : a32;  // d=lane and d=lane+32: same parity
        float acc1 = a0 + sgn, acc2 = a0 + sgn;
        #pragma unroll
        for (int e = 1; e < 32; ++e) {
            float2 Xe = ub[warp][e];
            int j1 = (e * lane) & 63;
            int j2 = (e * (lane + 32)) & 63;
            acc1 += 2.f * (Xe.x*tc[j1] - Xe.y*ts[j1]);
            acc2 += 2.f * (Xe.x*tc[j2] - Xe.y*ts[j2]);
        }
        op[lane]      = acc1 * (1.0f/64.0f);
        op[lane + 32] = acc2 * (1.0f/64.0f);
    }
}

// ---------------- launch ----------------
extern "C" void kernel_launch(void* const* d_in, const int* in_sizes, int n_in,
                              void* d_out, int out_size)
{
    (void)in_sizes; (void)n_in; (void)out_size;
    const float* q = (const float*)d_in[0];
    const float* k = (const float*)d_in[1];
    const float* v = (const float*)d_in[2];
    const int* isamp = (const int*)d_in[4];
    float* out = (float*)d_out;

    k_rfft     <<<dim3(ROWS/8, 3), 256>>>(q, k, v);
    k_transpose<<<dim3(LL/32, BHN), 256>>>();
    k_vmean    <<<BHN, 96>>>();
    k_msample  <<<ROWS/4, 128>>>(isamp);
    k_topk     <<<BHN, 256>>>();
    k_scores   <<<dim3(4, 2, BHN), 512>>>();
    k_softmax  <<<BHN*UU, 256>>>();
    k_upd      <<<dim3(5, BHN), 256>>>();
    k_vmt      <<<BHN, 64>>>();
    k_out      <<<ROWS/8, 256>>>(out);
}

// round 3
// speedup vs baseline: 1.7269x; 1.7269x over previous
#include <cuda_runtime.h>
#include <cstdint>
#include <cstddef>

#define BB 8
#define LL 2048
#define HH 8
#define DD 64
#define EE 33
#define UU 40
#define SK 40
#define BHN (BB*HH)
#define ROWS (BHN*LL)

// ---------------- static scratch ----------------
__device__ float2 g_qf [ROWS*EE];
__device__ float2 g_kf [ROWS*EE];
__device__ float2 g_vf [ROWS*EE];
__device__ float2 g_kfT[ROWS*EE];
__device__ float  g_M  [ROWS];
__device__ int    g_top [BHN*UU];
__device__ int    g_slot[ROWS];
__device__ float2 g_upd [BHN*UU*EE];
__device__ float  g_vmt[BHN*DD];
__device__ float2 g_big [(size_t)BHN*UU*LL];

__device__ __forceinline__ void cpa8(void* s, const void* g) {
    unsigned sa = (unsigned)__cvta_generic_to_shared(s);
    asm volatile("cp.async.ca.shared.global [%0], [%1], 8;" :: "r"(sa), "l"(g));
}
__device__ __forceinline__ void cp_wait_all() {
    asm volatile("cp.async.wait_all;" ::: "memory");
}

// ---------------- K1: rfft via 32-pt complex DFT + untangle ----------------
__global__ void k_rfft(const float* __restrict__ q,
                       const float* __restrict__ k,
                       const float* __restrict__ v)
{
    __shared__ float2 w32[32], w64[32];
    __shared__ float2 zs[8][32];
    int tid = threadIdx.x;
    if (tid < 32) {
        float s, c;
        sincospif(tid * (1.0f/16.0f), &s, &c);  // 2*pi*tid/32
        w32[tid] = make_float2(c, -s);
        sincospif(tid * (1.0f/32.0f), &s, &c);  // 2*pi*tid/64
        w64[tid] = make_float2(c, -s);
    }
    __syncthreads();
    int warp = tid >> 5, lane = tid & 31;
    int r  = blockIdx.x * 8 + warp;              // r = bh*L + l
    int l  = r & (LL - 1);
    int bh = r >> 11;
    int b = bh >> 3, h = bh & 7;
    const float* src = (blockIdx.y == 0) ? q : (blockIdx.y == 1) ? k : v;
    const float2* x2 = (const float2*)(src + (((size_t)b*LL + l)*HH + h) * DD);
    float2 z = x2[lane];                         // z[n] = x[2n] + i x[2n+1]
    zs[warp][lane] = z;
    __syncwarp();
    // 32-pt complex DFT: lane = output bin
    float Zr = 0.f, Zi = 0.f;
    int j = 0;
    #pragma unroll
    for (int n = 0; n < 32; ++n) {
        float2 zn = zs[warp][n];
        float2 w  = w32[j];
        Zr = fmaf(zn.x, w.x, Zr); Zr = fmaf(-zn.y, w.y, Zr);
        Zi = fmaf(zn.x, w.y, Zi); Zi = fmaf( zn.y, w.x, Zi);
        j = (j + lane) & 31;
    }
    // untangle: E = (Z + conj(Zm))/2, O = -i(Z - conj(Zm))/2, X = E + W64^k O
    int srcl = (32 - lane) & 31;
    float Zmr = __shfl_sync(0xffffffffu, Zr, srcl);
    float Zmi = __shfl_sync(0xffffffffu, Zi, srcl);
    float Zer = 0.5f*(Zr + Zmr), Zei = 0.5f*(Zi - Zmi);
    float Zor = 0.5f*(Zi + Zmi), Zoi = -0.5f*(Zr - Zmr);
    float2 w = w64[lane];
    float Xr = Zer + w.x*Zor - w.y*Zoi;
    float Xi = Zei + w.x*Zoi + w.y*Zor;
    float2* out = (blockIdx.y == 0) ? g_qf : (blockIdx.y == 1) ? g_kf : g_vf;
    out[(size_t)r*EE + lane] = make_float2(Xr, Xi);
    if (lane == 0) out[(size_t)r*EE + 32] = make_float2(Zr - Zi, 0.f);  // X[32] = Re(Z0)-Im(Z0)
}

// ---------------- K2: transpose k_fft -> (bh, e, l) ----------------
__global__ void k_transpose()
{
    __shared__ float2 tile[32][EE];
    int bh = blockIdx.y;
    int l0 = blockIdx.x * 32;
    for (int t = threadIdx.x; t < 32*EE; t += 256) {
        int r = t / EE, e = t - r*EE;
        tile[r][e] = g_kf[((size_t)bh*LL + l0 + r)*EE + e];
    }
    __syncthreads();
    for (int t = threadIdx.x; t < EE*32; t += 256) {
        int e = t >> 5, r = t & 31;
        g_kfT[((size_t)bh*EE + e)*LL + l0 + r] = tile[r][e];
    }
}

// ---------------- K2b: time-domain v mean (== irfft(mean(rfft(v)))) ----------------
__global__ void k_vmt(const float* __restrict__ v)
{
    __shared__ float part[8][64];
    int bh = blockIdx.x, b = bh >> 3, h = bh & 7;
    int tid = threadIdx.x;              // 512 threads
    int d = tid & 63, g = tid >> 6;     // 8 l-groups
    const float* base = v + (((size_t)b*LL)*HH + h) * DD + d;
    float acc = 0.f;
    #pragma unroll 8
    for (int i = g; i < LL; i += 8) acc += base[(size_t)i * (HH*DD)];
    part[g][d] = acc;
    __syncthreads();
    if (tid < 64) {
        float s = 0.f;
        #pragma unroll
        for (int g2 = 0; g2 < 8; ++g2) s += part[g2][tid];
        g_vmt[bh*DD + tid] = s * (1.0f/LL);
    }
}

// ---------------- K3: sampled QK -> M (cp.async staged, e-split) ----------------
__global__ void __launch_bounds__(256) k_msample(const int* __restrict__ isamp)
{
    __shared__ float2 kbuf[8][SK][17];
    __shared__ float2 qbuf[8][EE];
    int tid = threadIdx.x;
    int warp = tid >> 5, lane = tid & 31;
    int r  = blockIdx.x * 8 + warp;
    int l  = r & (LL - 1);
    int bh = r >> 11;
    const int* iss = isamp + l * SK;
    int idxA = iss[lane];
    int idxB = (lane < 8) ? iss[32 + lane] : 0;
    qbuf[warp][lane] = g_qf[(size_t)r*EE + lane];
    if (lane == 0) qbuf[warp][32] = g_qf[(size_t)r*EE + 32];
    const float2* kb = g_kf + (size_t)bh*LL*EE;
    // phase A: e in [0,17)
    #pragma unroll 8
    for (int s = 0; s < SK; ++s) {
        int id = (s < 32) ? __shfl_sync(0xffffffffu, idxA, s)
                          : __shfl_sync(0xffffffffu, idxB, s - 32);
        if (lane < 17) cpa8(&kbuf[warp][s][lane], &kb[(size_t)id*EE + lane]);
    }
    cp_wait_all(); __syncwarp();
    float dR = 0.f, dI = 0.f, dR2 = 0.f, dI2 = 0.f;
    #pragma unroll
    for (int e = 0; e < 17; ++e) {
        float2 qv = qbuf[warp][e];
        float2 kv = kbuf[warp][lane][e];
        dR = fmaf(qv.x, kv.x, dR); dR = fmaf(-qv.y, kv.y, dR);
        dI = fmaf(qv.x, kv.y, dI); dI = fmaf( qv.y, kv.x, dI);
    }
    if (lane < 8) {
        #pragma unroll
        for (int e = 0; e < 17; ++e) {
            float2 qv = qbuf[warp][e];
            float2 kv = kbuf[warp][32 + lane][e];
            dR2 = fmaf(qv.x, kv.x, dR2); dR2 = fmaf(-qv.y, kv.y, dR2);
            dI2 = fmaf(qv.x, kv.y, dI2); dI2 = fmaf( qv.y, kv.x, dI2);
        }
    }
    __syncwarp();
    // phase B: e in [17,33)
    #pragma unroll 8
    for (int s = 0; s < SK; ++s) {
        int id = (s < 32) ? __shfl_sync(0xffffffffu, idxA, s)
                          : __shfl_sync(0xffffffffu, idxB, s - 32);
        if (lane < 16) cpa8(&kbuf[warp][s][lane], &kb[(size_t)id*EE + 17 + lane]);
    }
    cp_wait_all(); __syncwarp();
    #pragma unroll
    for (int e = 0; e < 16; ++e) {
        float2 qv = qbuf[warp][17 + e];
        float2 kv = kbuf[warp][lane][e];
        dR = fmaf(qv.x, kv.x, dR); dR = fmaf(-qv.y, kv.y, dR);
        dI = fmaf(qv.x, kv.y, dI); dI = fmaf( qv.y, kv.x, dI);
    }
    if (lane < 8) {
        #pragma unroll
        for (int e = 0; e < 16; ++e) {
            float2 qv = qbuf[warp][17 + e];
            float2 kv = kbuf[warp][32 + lane][e];
            dR2 = fmaf(qv.x, kv.x, dR2); dR2 = fmaf(-qv.y, kv.y, dR2);
            dI2 = fmaf(qv.x, kv.y, dI2); dI2 = fmaf( qv.y, kv.x, dI2);
        }
    }
    float mre = dR, mim = dI, sre = dR, sim = dI;
    if (lane < 8) {
        mre = fmaxf(mre, dR2); mim = fmaxf(mim, dI2);
        sre += dR2; sim += dI2;
    }
    #pragma unroll
    for (int o = 16; o; o >>= 1) {
        mre = fmaxf(mre, __shfl_xor_sync(0xffffffffu, mre, o));
        mim = fmaxf(mim, __shfl_xor_sync(0xffffffffu, mim, o));
        sre += __shfl_xor_sync(0xffffffffu, sre, o);
        sim += __shfl_xor_sync(0xffffffffu, sim, o);
    }
    if (lane == 0) g_M[r] = mre + mim - (sre + sim) * (1.0f/LL);
}

// ---------------- K4: top-40 per bh (warp-shuffle argmax) ----------------
__global__ void k_topk()
{
    __shared__ float mv[LL];
    __shared__ float wv[8];
    __shared__ int   wi[8];
    int bh = blockIdx.x, tid = threadIdx.x, lane = tid & 31, warp = tid >> 5;
    for (int i = tid; i < LL; i += 256) {
        mv[i] = g_M[bh*LL + i];
        g_slot[bh*LL + i] = -1;
    }
    __syncthreads();
    for (int u = 0; u < UU; ++u) {
        float best = -3.4e38f; int bi = 1 << 30;
        for (int i = tid; i < LL; i += 256) {
            float x = mv[i];
            if (x > best) { best = x; bi = i; }      // earliest in-stride kept
        }
        #pragma unroll
        for (int o = 16; o; o >>= 1) {
            float ov = __shfl_xor_sync(0xffffffffu, best, o);
            int   oi = __shfl_xor_sync(0xffffffffu, bi, o);
            if (ov > best || (ov == best && oi < bi)) { best = ov; bi = oi; }
        }
        if (lane == 0) { wv[warp] = best; wi[warp] = bi; }
        __syncthreads();
        if (warp == 0) {
            float b2 = (lane < 8) ? wv[lane] : -3.4e38f;
            int   i2 = (lane < 8) ? wi[lane] : (1 << 30);
            #pragma unroll
            for (int o = 4; o; o >>= 1) {
                float ov = __shfl_xor_sync(0xffffffffu, b2, o);
                int   oi = __shfl_xor_sync(0xffffffffu, i2, o);
                if (ov > b2 || (ov == b2 && oi < i2)) { b2 = ov; i2 = oi; }
            }
            if (lane == 0) {
                g_top[bh*UU + u] = i2;
                g_slot[bh*LL + i2] = u;
                mv[i2] = -3.4e38f;
            }
        }
        __syncthreads();
    }
}

// ---------------- K5: full scores, 20-u register blocked ----------------
__global__ void __launch_bounds__(512) k_scores()
{
    __shared__ float2 shq[20][EE];
    int bh = blockIdx.z;
    int ug = blockIdx.y;     // 0..1
    int jt = blockIdx.x;     // 0..3
    int tid = threadIdx.x;
    for (int t = tid; t < 20*EE; t += 512) {
        int ul = t / EE, e = t - ul*EE;
        int qi = g_top[bh*UU + ug*20 + ul];
        shq[ul][e] = g_qf[((size_t)bh*LL + qi)*EE + e];
    }
    __syncthreads();
    int j = jt*512 + tid;
    float accR[20], accI[20];
    #pragma unroll
    for (int u = 0; u < 20; ++u) { accR[u] = 0.f; accI[u] = 0.f; }
    const float2* kT = g_kfT + (size_t)bh*EE*LL + j;
    for (int e = 0; e < EE; ++e) {
        float2 kv = kT[(size_t)e*LL];
        #pragma unroll
        for (int u = 0; u < 20; ++u) {
            float2 qv = shq[u][e];
            accR[u] = fmaf(qv.x, kv.x, accR[u]); accR[u] = fmaf(-qv.y, kv.y, accR[u]);
            accI[u] = fmaf(qv.x, kv.y, accI[u]); accI[u] = fmaf( qv.y, kv.x, accI[u]);
        }
    }
    const float sc = 0.125f;   // 1/sqrt(64)
    #pragma unroll
    for (int u = 0; u < 20; ++u)
        g_big[((size_t)bh*UU + ug*20 + u)*LL + j] = make_float2(accR[u]*sc, accI[u]*sc);
}

// ---------------- K5b: softmax over real & imag channels ----------------
__global__ void k_softmax()
{
    __shared__ float2 sb[LL];
    __shared__ float2 red[256];
    int row = blockIdx.x, tid = threadIdx.x;
    float2* rp = g_big + (size_t)row*LL;
    float mr = -3.4e38f, mi = -3.4e38f;
    for (int i = tid; i < LL; i += 256) {
        float2 v = rp[i]; sb[i] = v;
        mr = fmaxf(mr, v.x); mi = fmaxf(mi, v.y);
    }
    red[tid] = make_float2(mr, mi);
    __syncthreads();
    for (int s = 128; s; s >>= 1) {
        if (tid < s) {
            red[tid].x = fmaxf(red[tid].x, red[tid+s].x);
            red[tid].y = fmaxf(red[tid].y, red[tid+s].y);
        }
        __syncthreads();
    }
    mr = red[0].x; mi = red[0].y;
    __syncthreads();
    float sr = 0.f, si = 0.f;
    for (int i = tid; i < LL; i += 256) {
        float er = __expf(sb[i].x - mr);
        float ei = __expf(sb[i].y - mi);
        sb[i] = make_float2(er, ei);
        sr += er; si += ei;
    }
    red[tid] = make_float2(sr, si);
    __syncthreads();
    for (int s = 128; s; s >>= 1) {
        if (tid < s) { red[tid].x += red[tid+s].x; red[tid].y += red[tid+s].y; }
        __syncthreads();
    }
    float inr = 1.0f / red[0].x, ini = 1.0f / red[0].y;
    for (int i = tid; i < LL; i += 256)
        rp[i] = make_float2(sb[i].x * inr, sb[i].y * ini);
}

// ---------------- K6: upd = attn_r @ v.re + i * attn_i @ v.im ----------------
__global__ void __launch_bounds__(256) k_upd()
{
    __shared__ float2 sp[8][256];
    __shared__ float2 accs[8][8][EE];
    int bh = blockIdx.y, ug = blockIdx.x;
    int tid = threadIdx.x, warp = tid >> 5, lane = tid & 31;
    float aR[8], aI[8], aR2[8], aI2[8];
    #pragma unroll
    for (int u = 0; u < 8; ++u) { aR[u]=aI[u]=aR2[u]=aI2[u]=0.f; }
    const float2* vb = g_vf + (size_t)bh*LL*EE;
    for (int c = 0; c < 8; ++c) {
        #pragma unroll
        for (int u = 0; u < 8; ++u)
            sp[u][tid] = g_big[((size_t)bh*UU + ug*8 + u)*LL + c*256 + tid];
        __syncthreads();
        for (int li = warp; li < 256; li += 8) {
            int l = c*256 + li;
            float2 v2 = vb[(size_t)l*EE + lane];
            float2 v32 = make_float2(0.f, 0.f);
            if (lane == 0) v32 = vb[(size_t)l*EE + 32];
            #pragma unroll
            for (int u = 0; u < 8; ++u) {
                float2 p = sp[u][li];
                aR[u]  = fmaf(p.x, v2.x,  aR[u]);
                aI[u]  = fmaf(p.y, v2.y,  aI[u]);
                aR2[u] = fmaf(p.x, v32.x, aR2[u]);
                aI2[u] = fmaf(p.y, v32.y, aI2[u]);
            }
        }
        __syncthreads();
    }
    #pragma unroll
    for (int u = 0; u < 8; ++u) {
        accs[warp][u][lane] = make_float2(aR[u], aI[u]);
        if (lane == 0) accs[warp][u][32] = make_float2(aR2[u], aI2[u]);
    }
    __syncthreads();
    for (int t = tid; t < 8*EE; t += 256) {
        int u = t / EE, e = t - u*EE;
        float sr = 0.f, si = 0.f;
        #pragma unroll
        for (int w = 0; w < 8; ++w) { sr += accs[w][u][e].x; si += accs[w][u][e].y; }
        g_upd[((size_t)bh*UU + ug*8 + u)*EE + e] = make_float2(sr, si);
    }
}

// ---------------- K7: scatter + irfft of selected rows ----------------
__global__ void k_out(float* __restrict__ out)
{
    __shared__ float tc[64], ts[64];
    __shared__ float2 ub[8][EE];
    int tid = threadIdx.x;
    if (tid < 64) {
        float s, c;
        sincospif(tid * (1.0f/32.0f), &s, &c);
        tc[tid] = c; ts[tid] = s;
    }
    __syncthreads();
    int warp = tid >> 5, lane = tid & 31;
    int r = blockIdx.x * 8 + warp;
    int bh = r >> 11;
    int slot = g_slot[r];
    float* op = out + (size_t)r * DD;
    if (slot < 0) {
        op[lane]      = g_vmt[bh*DD + lane];
        op[lane + 32] = g_vmt[bh*DD + lane + 32];
    } else {
        const float2* X = g_upd + ((size_t)bh*UU + slot)*EE;
        ub[warp][lane] = X[lane];
        if (lane == 0) ub[warp][32] = X[32];
        __syncwarp();
        float a0 = ub[warp][0].x;
        float a32 = ub[warp][32].x;
        float sgn = (lane & 1) ? -a32 : a32;
        float acc1 = a0 + sgn, acc2 = a0 + sgn;
        #pragma unroll
        for (int e = 1; e < 32; ++e) {
            float2 Xe = ub[warp][e];
            int j1 = (e * lane) & 63;
            int j2 = (e * (lane + 32)) & 63;
            acc1 += 2.f * (Xe.x*tc[j1] - Xe.y*ts[j1]);
            acc2 += 2.f * (Xe.x*tc[j2] - Xe.y*ts[j2]);
        }
        op[lane]      = acc1 * (1.0f/64.0f);
        op[lane + 32] = acc2 * (1.0f/64.0f);
    }
}

// ---------------- launch ----------------
extern "C" void kernel_launch(void* const* d_in, const int* in_sizes, int n_in,
                              void* d_out, int out_size)
{
    (void)in_sizes; (void)n_in; (void)out_size;
    const float* q = (const float*)d_in[0];
    const float* k = (const float*)d_in[1];
    const float* v = (const float*)d_in[2];
    const int* isamp = (const int*)d_in[4];
    float* out = (float*)d_out;

    k_rfft     <<<dim3(ROWS/8, 3), 256>>>(q, k, v);
    k_transpose<<<dim3(LL/32, BHN), 256>>>();
    k_vmt      <<<BHN, 512>>>(v);
    k_msample  <<<ROWS/8, 256>>>(isamp);
    k_topk     <<<BHN, 256>>>();
    k_scores   <<<dim3(4, 2, BHN), 512>>>();
    k_softmax  <<<BHN*UU, 256>>>();
    k_upd      <<<dim3(5, BHN), 256>>>();
    k_out      <<<ROWS/8, 256>>>(out);
}